// round 1
// baseline (speedup 1.0000x reference)
#include <cuda_runtime.h>
#include <math.h>

#define T_STEPS 256
#define BSZ 32
#define VOCAB 32000
#define EMB 512
#define HID 1024
#define G4 4096
#define TB (T_STEPS*BSZ)   // 8192

// ---------------- scratch (device globals; no allocation allowed) ----------------
__device__ float g_x[TB*EMB];          // 16.8 MB  embedding output
__device__ float g_gates[(size_t)TB*G4]; // 134 MB input-projection gates (per layer, reused)
__device__ float g_seqA[(size_t)TB*HID]; // 33.5 MB layer output ping
__device__ float g_seqB[(size_t)TB*HID]; // 33.5 MB layer output pong
__device__ float g_h0[BSZ*HID];        // zero initial h
__device__ float g_c[BSZ*HID];         // cell state

// ---------------- f32x2 packed helpers (sm_103a) ----------------
__device__ __forceinline__ void fma2(unsigned long long &d, unsigned long long a, unsigned long long b){
    asm("fma.rn.f32x2 %0, %1, %2, %0;" : "+l"(d) : "l"(a), "l"(b));
}
__device__ __forceinline__ unsigned long long pk2(float lo, float hi){
    unsigned long long r; asm("mov.b64 %0, {%1, %2};" : "=l"(r) : "f"(lo), "f"(hi)); return r;
}
__device__ __forceinline__ float2 upk2(unsigned long long v){
    float2 r; asm("mov.b64 {%0, %1}, %2;" : "=f"(r.x), "=f"(r.y) : "l"(v)); return r;
}

__device__ __forceinline__ float sigm(float x){ return 1.0f / (1.0f + expf(-x)); }

// ---------------- embedding gather ----------------
__global__ void embed_k(const int* __restrict__ data, const float* __restrict__ emb,
                        float* __restrict__ out){
    int idx = blockIdx.x * 256 + threadIdx.x;      // over TB*EMB/4 float4s
    int e4 = idx & (EMB/4 - 1);
    int tb = idx >> 7;                              // EMB/4 = 128 = 2^7
    ((float4*)out)[idx] = ((const float4*)(emb + (size_t)data[tb]*EMB))[e4];
}

// ---------------- SGEMM: C[M,N] = A[M,K] @ B[K,N] + bias[N] ----------------
// 128x128 block tile, BK=16, 256 threads, 8x8 microtile, f32x2 packed FMA.
// Requires M%128==0, N%128==0, K%16==0 (true for all calls here).
__global__ __launch_bounds__(256, 2)
void sgemm_bias(const float* __restrict__ A, const float* __restrict__ Bm,
                const float* __restrict__ bias, float* __restrict__ C,
                int M, int N, int K){
    __shared__ __align__(16) float As[16][128];
    __shared__ __align__(16) float Bs[16][128];
    const int tid = threadIdx.x;
    const int r0 = blockIdx.y * 128;
    const int c0 = blockIdx.x * 128;
    const int tx = tid & 15;
    const int ty = tid >> 4;

    unsigned long long acc[8][4];
    #pragma unroll
    for (int i = 0; i < 8; i++)
        #pragma unroll
        for (int j = 0; j < 4; j++) acc[i][j] = 0ULL;   // two packed 0.0f

    for (int k0 = 0; k0 < K; k0 += 16){
        #pragma unroll
        for (int l = 0; l < 2; l++){
            int id = tid + l*256;
            // A tile: 128 rows x 16 cols, transpose into As[k][row]
            int ar = id >> 2, ac = (id & 3) * 4;
            float4 va = *(const float4*)(A + (size_t)(r0 + ar)*K + k0 + ac);
            As[ac+0][ar] = va.x; As[ac+1][ar] = va.y; As[ac+2][ar] = va.z; As[ac+3][ar] = va.w;
            // B tile: 16 rows x 128 cols, direct
            int br = id >> 5, bc = (id & 31) * 4;
            *(float4*)&Bs[br][bc] = *(const float4*)(Bm + (size_t)(k0 + br)*N + c0 + bc);
        }
        __syncthreads();
        #pragma unroll
        for (int k = 0; k < 16; k++){
            float4 a0 = *(const float4*)&As[k][ty*8];
            float4 a1 = *(const float4*)&As[k][ty*8 + 4];
            float4 b0 = *(const float4*)&Bs[k][tx*8];
            float4 b1 = *(const float4*)&Bs[k][tx*8 + 4];
            unsigned long long pb0 = pk2(b0.x, b0.y);
            unsigned long long pb1 = pk2(b0.z, b0.w);
            unsigned long long pb2 = pk2(b1.x, b1.y);
            unsigned long long pb3 = pk2(b1.z, b1.w);
            float av[8] = {a0.x, a0.y, a0.z, a0.w, a1.x, a1.y, a1.z, a1.w};
            #pragma unroll
            for (int i = 0; i < 8; i++){
                unsigned long long aa = pk2(av[i], av[i]);
                fma2(acc[i][0], aa, pb0);
                fma2(acc[i][1], aa, pb1);
                fma2(acc[i][2], aa, pb2);
                fma2(acc[i][3], aa, pb3);
            }
        }
        __syncthreads();
    }

    #pragma unroll
    for (int i = 0; i < 8; i++){
        size_t row = (size_t)(r0 + ty*8 + i);
        int col = c0 + tx*8;
        float out[8];
        #pragma unroll
        for (int j = 0; j < 4; j++){
            float2 v = upk2(acc[i][j]);
            out[j*2]   = v.x + bias[col + j*2];
            out[j*2+1] = v.y + bias[col + j*2 + 1];
        }
        *(float4*)(C + row*N + col)     = make_float4(out[0], out[1], out[2], out[3]);
        *(float4*)(C + row*N + col + 4) = make_float4(out[4], out[5], out[6], out[7]);
    }
}

// ---------------- fused recurrent step ----------------
// gates(t) = gin(t) + h(t-1) @ Wh ; then state update.
// Grid: 128 blocks (8 hidden units each), 128 threads (b = tid&31, gate u = tid>>5).
#define CK 64
__global__ __launch_bounds__(128, 1)
void lstm_step(const float* __restrict__ gin,    // [32, 4096] (input proj + bias, this t)
               const float* __restrict__ Wh,     // [1024, 4096] row-major
               const float* __restrict__ hprev,  // [32, 1024]
               float* __restrict__ c,            // [32, 1024] in/out
               float* __restrict__ hout)         // [32, 1024] (= layer output at t)
{
    __shared__ __align__(16) float sh[32][CK + 1];   // h chunk (padded vs bank conflict)
    __shared__ __align__(16) float sw[CK][32];       // W chunk: col = gate*8 + hul
    __shared__ float res[4][8][33];                  // [gate][hul][b]

    const int tid = threadIdx.x;
    const int b = tid & 31;
    const int u = tid >> 5;                  // gate index 0..3
    const int hu0 = blockIdx.x * 8;

    float acc[8] = {0.f,0.f,0.f,0.f,0.f,0.f,0.f,0.f};

    for (int k0 = 0; k0 < HID; k0 += CK){
        // load h chunk: 32 x CK floats
        #pragma unroll
        for (int l = 0; l < 4; l++){
            int id = tid + l*128;
            int hb = id >> 4;               // CK/4 = 16 float4 per row
            int kq = (id & 15) * 4;
            float4 v = *(const float4*)(hprev + hb*HID + k0 + kq);
            sh[hb][kq] = v.x; sh[hb][kq+1] = v.y; sh[hb][kq+2] = v.z; sh[hb][kq+3] = v.w;
        }
        // load W chunk: CK rows x 32 cols (4 gates x 8 units)
        #pragma unroll
        for (int l = 0; l < 4; l++){
            int id = tid + l*128;
            int k = id >> 3;                // 8 float4 per row
            int cq = (id & 7) * 4;          // 0,4,...,28
            int gate = cq >> 3, hul = cq & 7;
            float4 v = *(const float4*)(Wh + (size_t)(k0 + k)*G4 + gate*HID + hu0 + hul);
            *(float4*)&sw[k][cq] = v;
        }
        __syncthreads();
        #pragma unroll
        for (int kk = 0; kk < CK; kk++){
            float hv = sh[b][kk];
            float4 w0 = *(const float4*)&sw[kk][u*8];
            float4 w1 = *(const float4*)&sw[kk][u*8 + 4];
            acc[0] += hv * w0.x; acc[1] += hv * w0.y;
            acc[2] += hv * w0.z; acc[3] += hv * w0.w;
            acc[4] += hv * w1.x; acc[5] += hv * w1.y;
            acc[6] += hv * w1.z; acc[7] += hv * w1.w;
        }
        __syncthreads();
    }

    #pragma unroll
    for (int hul = 0; hul < 8; hul++) res[u][hul][b] = acc[hul];
    __syncthreads();

    #pragma unroll
    for (int l = 0; l < 2; l++){
        int item = tid + l*128;
        int bb = item & 31;
        int hul = item >> 5;                // 0..7
        int j = hu0 + hul;
        const float* gb = gin + (size_t)bb * G4;
        float iv = res[0][hul][bb] + gb[j];
        float gv = res[1][hul][bb] + gb[HID + j];
        float fv = res[2][hul][bb] + gb[2*HID + j];
        float ov = res[3][hul][bb] + gb[3*HID + j];
        float cprev = c[bb*HID + j];
        float cv = sigm(fv + 1.0f) * cprev + sigm(iv) * tanhf(gv);
        float hv = sigm(ov) * tanhf(cv);
        c[bb*HID + j] = cv;
        hout[bb*HID + j] = hv;
    }
}

// ---------------- launch ----------------
extern "C" void kernel_launch(void* const* d_in, const int* in_sizes, int n_in,
                              void* d_out, int out_size){
    (void)in_sizes; (void)n_in; (void)out_size;
    const int*   data = (const int*)d_in[0];
    const float* emb  = (const float*)d_in[2];
    const float* W[3]  = {(const float*)d_in[3], (const float*)d_in[5], (const float*)d_in[7]};
    const float* bs[3] = {(const float*)d_in[4], (const float*)d_in[6], (const float*)d_in[8]};
    const float* Wd = (const float*)d_in[9];
    const float* bd = (const float*)d_in[10];

    float *x, *gates, *seqA, *seqB, *h0, *cc;
    cudaGetSymbolAddress((void**)&x,     g_x);
    cudaGetSymbolAddress((void**)&gates, g_gates);
    cudaGetSymbolAddress((void**)&seqA,  g_seqA);
    cudaGetSymbolAddress((void**)&seqB,  g_seqB);
    cudaGetSymbolAddress((void**)&h0,    g_h0);
    cudaGetSymbolAddress((void**)&cc,    g_c);

    // 1) embedding gather
    embed_k<<<TB*EMB/4/256, 256>>>(data, emb, x);

    const float* in = x;
    float* outseq = seqA;
    for (int L = 0; L < 3; L++){
        int Din = (L == 0) ? EMB : HID;
        // 2) input projection for all timesteps: gates = in @ W[:Din] + b
        dim3 gp(G4/128, TB/128);
        sgemm_bias<<<gp, 256>>>(in, W[L], bs[L], gates, TB, G4, Din);
        // 3) zero states
        cudaMemsetAsync(cc, 0, BSZ*HID*sizeof(float));
        cudaMemsetAsync(h0, 0, BSZ*HID*sizeof(float));
        // 4) sequential recurrence
        const float* Wh = W[L] + (size_t)Din * G4;
        for (int t = 0; t < T_STEPS; t++){
            const float* hp = (t == 0) ? h0 : outseq + (size_t)(t-1)*BSZ*HID;
            lstm_step<<<HID/8, 128>>>(gates + (size_t)t*BSZ*G4, Wh, hp, cc,
                                      outseq + (size_t)t*BSZ*HID);
        }
        in = outseq;
        outseq = (outseq == seqA) ? seqB : seqA;
    }

    // 5) decoder: logits = in @ Wd + bd
    dim3 gd(VOCAB/128, TB/128);
    sgemm_bias<<<gd, 256>>>(in, Wd, bd, (float*)d_out, TB, VOCAB, HID);
}

// round 2
// speedup vs baseline: 1.7947x; 1.7947x over previous
#include <cuda_runtime.h>
#include <math.h>

#define T_STEPS 256
#define BSZ 32
#define VOCAB 32000
#define EMB 512
#define HID 1024
#define G4 4096
#define TB (T_STEPS*BSZ)   // 8192

// ---------------- scratch (device globals; no allocation allowed) ----------------
__device__ float g_x[TB*EMB];              // 16.8 MB  embedding output
__device__ float g_gates[(size_t)TB*G4];   // 134 MB input-projection gates (per layer, reused)
__device__ float g_seqA[(size_t)TB*HID];   // 33.5 MB layer output ping
__device__ float g_seqB[(size_t)TB*HID];   // 33.5 MB layer output pong

// grid barrier state
__device__ unsigned g_bar_count = 0;
__device__ volatile unsigned g_bar_sense = 0;

// ---------------- f32x2 packed helpers (sm_103a) ----------------
__device__ __forceinline__ void fma2(unsigned long long &d, unsigned long long a, unsigned long long b){
    asm("fma.rn.f32x2 %0, %1, %2, %0;" : "+l"(d) : "l"(a), "l"(b));
}
__device__ __forceinline__ unsigned long long pk2(float lo, float hi){
    unsigned long long r; asm("mov.b64 %0, {%1, %2};" : "=l"(r) : "f"(lo), "f"(hi)); return r;
}
__device__ __forceinline__ float2 upk2(unsigned long long v){
    float2 r; asm("mov.b64 {%0, %1}, %2;" : "=f"(r.x), "=f"(r.y) : "l"(v)); return r;
}
__device__ __forceinline__ float sigm(float x){ return 1.0f / (1.0f + expf(-x)); }

// ---------------- embedding gather ----------------
__global__ void embed_k(const int* __restrict__ data, const float* __restrict__ emb,
                        float* __restrict__ out){
    int idx = blockIdx.x * 256 + threadIdx.x;      // over TB*EMB/4 float4s
    int e4 = idx & (EMB/4 - 1);
    int tb = idx >> 7;                              // EMB/4 = 128 = 2^7
    ((float4*)out)[idx] = ((const float4*)(emb + (size_t)data[tb]*EMB))[e4];
}

// ---------------- SGEMM: C[M,N] = A[M,K] @ B[K,N] + bias[N] ----------------
__global__ __launch_bounds__(256, 2)
void sgemm_bias(const float* __restrict__ A, const float* __restrict__ Bm,
                const float* __restrict__ bias, float* __restrict__ C,
                int M, int N, int K){
    __shared__ __align__(16) float As[16][128];
    __shared__ __align__(16) float Bs[16][128];
    const int tid = threadIdx.x;
    const int r0 = blockIdx.y * 128;
    const int c0 = blockIdx.x * 128;
    const int tx = tid & 15;
    const int ty = tid >> 4;

    unsigned long long acc[8][4];
    #pragma unroll
    for (int i = 0; i < 8; i++)
        #pragma unroll
        for (int j = 0; j < 4; j++) acc[i][j] = 0ULL;

    for (int k0 = 0; k0 < K; k0 += 16){
        #pragma unroll
        for (int l = 0; l < 2; l++){
            int id = tid + l*256;
            int ar = id >> 2, ac = (id & 3) * 4;
            float4 va = *(const float4*)(A + (size_t)(r0 + ar)*K + k0 + ac);
            As[ac+0][ar] = va.x; As[ac+1][ar] = va.y; As[ac+2][ar] = va.z; As[ac+3][ar] = va.w;
            int br = id >> 5, bc = (id & 31) * 4;
            *(float4*)&Bs[br][bc] = *(const float4*)(Bm + (size_t)(k0 + br)*N + c0 + bc);
        }
        __syncthreads();
        #pragma unroll
        for (int k = 0; k < 16; k++){
            float4 a0 = *(const float4*)&As[k][ty*8];
            float4 a1 = *(const float4*)&As[k][ty*8 + 4];
            float4 b0 = *(const float4*)&Bs[k][tx*8];
            float4 b1 = *(const float4*)&Bs[k][tx*8 + 4];
            unsigned long long pb0 = pk2(b0.x, b0.y);
            unsigned long long pb1 = pk2(b0.z, b0.w);
            unsigned long long pb2 = pk2(b1.x, b1.y);
            unsigned long long pb3 = pk2(b1.z, b1.w);
            float av[8] = {a0.x, a0.y, a0.z, a0.w, a1.x, a1.y, a1.z, a1.w};
            #pragma unroll
            for (int i = 0; i < 8; i++){
                unsigned long long aa = pk2(av[i], av[i]);
                fma2(acc[i][0], aa, pb0);
                fma2(acc[i][1], aa, pb1);
                fma2(acc[i][2], aa, pb2);
                fma2(acc[i][3], aa, pb3);
            }
        }
        __syncthreads();
    }

    #pragma unroll
    for (int i = 0; i < 8; i++){
        size_t row = (size_t)(r0 + ty*8 + i);
        int col = c0 + tx*8;
        float out[8];
        #pragma unroll
        for (int j = 0; j < 4; j++){
            float2 v = upk2(acc[i][j]);
            out[j*2]   = v.x + bias[col + j*2];
            out[j*2+1] = v.y + bias[col + j*2 + 1];
        }
        *(float4*)(C + row*N + col)     = make_float4(out[0], out[1], out[2], out[3]);
        *(float4*)(C + row*N + col + 4) = make_float4(out[4], out[5], out[6], out[7]);
    }
}

// ---------------- persistent weight-stationary LSTM layer ----------------
// 128 blocks (1/SM, all co-resident), each owns 8 hidden units (32 gate cols).
// Wh slice [1024 x 32] pinned in SMEM for the whole layer. Grid barrier per step.
#define NBLK 128
// smem floats: sw 1024*32, sh 2*128*33, res 2*4*8*33, sc 8*33
#define SW_F   (1024*32)
#define SH_F   (2*128*33)
#define RES_F  (2*4*8*33)
#define SC_F   (8*33)
#define LSTM_SMEM_BYTES ((SW_F + SH_F + RES_F + SC_F) * 4)

__global__ __launch_bounds__(256, 1)
void lstm_layer_k(const float* __restrict__ gates_all,  // [T][32][4096] (x-proj + bias)
                  const float* __restrict__ Wh,         // [1024][4096]
                  float* seq)                           // [T][32][1024] layer output (h)
{
    extern __shared__ float smem[];
    float* sw  = smem;                   // [1024][32] cols: g*8+hu
    float* sh  = sw  + SW_F;             // [2][128][33] h chunk, [k][b] padded
    float* res = sh  + SH_F;             // [kh][g][hu][33]
    float* sc  = res + RES_F;            // [hu][33] cell state

    const int tid = threadIdx.x;
    const int hu0 = blockIdx.x * 8;

    // pin Wh slice in SMEM (once per layer)
    for (int i = tid; i < SW_F; i += 256){
        int k = i >> 5;
        int c = i & 31;
        int g = c >> 3, hu = c & 7;
        sw[i] = Wh[(size_t)k*G4 + g*HID + hu0 + hu];
    }
    // zero cell state
    for (int i = tid; i < SC_F; i += 256) sc[i] = 0.f;
    __syncthreads();

    unsigned phase = g_bar_sense;   // stable: no block flips before all have entered barrier 1

    const int b  = tid & 31;
    const int g  = (tid >> 5) & 3;
    const int kh = tid >> 7;            // split-k half

    for (int t = 0; t < T_STEPS; t++){
        unsigned long long acc[4] = {0ULL, 0ULL, 0ULL, 0ULL};

        if (t > 0){
            const float* hprev = seq + (size_t)(t-1)*BSZ*HID;  // plain ptr (no nc path)
            for (int cb = 0; cb < 4; cb++){
                // stage 2 half-chunks of h: k in [hh*512+cb*128, +128)
                for (int i = tid; i < 2048; i += 256){
                    int hh = i >> 10;
                    int r  = i & 1023;
                    int bb = r >> 5;
                    int jj = r & 31;
                    int kk = jj * 4;
                    int kbase = hh*512 + cb*128;
                    float4 v = *(const float4*)(hprev + (size_t)bb*HID + kbase + kk);
                    float* dst = sh + hh*128*33;
                    dst[(kk+0)*33 + bb] = v.x;
                    dst[(kk+1)*33 + bb] = v.y;
                    dst[(kk+2)*33 + bb] = v.z;
                    dst[(kk+3)*33 + bb] = v.w;
                }
                __syncthreads();
                const float* shh = sh + kh*128*33;
                const int kb = kh*512 + cb*128;
                #pragma unroll 4
                for (int kk = 0; kk < 128; kk++){
                    float hv = shh[kk*33 + b];
                    unsigned long long h2 = pk2(hv, hv);
                    const float4* wrow = (const float4*)(sw + (kb + kk)*32 + g*8);
                    float4 w0 = wrow[0];
                    float4 w1 = wrow[1];
                    fma2(acc[0], h2, pk2(w0.x, w0.y));
                    fma2(acc[1], h2, pk2(w0.z, w0.w));
                    fma2(acc[2], h2, pk2(w1.x, w1.y));
                    fma2(acc[3], h2, pk2(w1.z, w1.w));
                }
                __syncthreads();
            }
        }

        // write split-k partials: res[kh][g][hu][b]
        #pragma unroll
        for (int j = 0; j < 4; j++){
            float2 v = upk2(acc[j]);
            res[((kh*4 + g)*8 + j*2    )*33 + b] = v.x;
            res[((kh*4 + g)*8 + j*2 + 1)*33 + b] = v.y;
        }
        __syncthreads();

        // state update: tid -> (hu, bb)
        {
            int hu = tid >> 5;
            int bb = tid & 31;
            const float* gin = gates_all + (size_t)t*BSZ*G4 + (size_t)bb*G4 + hu0 + hu;
            float iv = res[((0*4+0)*8 + hu)*33 + bb] + res[((1*4+0)*8 + hu)*33 + bb] + gin[0];
            float gv = res[((0*4+1)*8 + hu)*33 + bb] + res[((1*4+1)*8 + hu)*33 + bb] + gin[HID];
            float fv = res[((0*4+2)*8 + hu)*33 + bb] + res[((1*4+2)*8 + hu)*33 + bb] + gin[2*HID];
            float ov = res[((0*4+3)*8 + hu)*33 + bb] + res[((1*4+3)*8 + hu)*33 + bb] + gin[3*HID];
            float cp = sc[hu*33 + bb];
            float cv = sigm(fv + 1.0f) * cp + sigm(iv) * tanhf(gv);
            float hv = sigm(ov) * tanhf(cv);
            sc[hu*33 + bb] = cv;
            seq[(size_t)t*BSZ*HID + (size_t)bb*HID + hu0 + hu] = hv;
        }

        // grid barrier (publishes seq[t] to all blocks)
        __syncthreads();
        if (tid == 0){
            __threadfence();
            unsigned old = atomicAdd(&g_bar_count, 1u);
            if (old == NBLK - 1){
                g_bar_count = 0;
                __threadfence();
                g_bar_sense = phase ^ 1u;
            } else {
                while (g_bar_sense != (phase ^ 1u)) { __nanosleep(64); }
            }
            __threadfence();
        }
        phase ^= 1u;
        __syncthreads();
    }
}

// ---------------- launch ----------------
extern "C" void kernel_launch(void* const* d_in, const int* in_sizes, int n_in,
                              void* d_out, int out_size){
    (void)in_sizes; (void)n_in; (void)out_size;
    const int*   data = (const int*)d_in[0];
    const float* emb  = (const float*)d_in[2];
    const float* W[3]  = {(const float*)d_in[3], (const float*)d_in[5], (const float*)d_in[7]};
    const float* bs[3] = {(const float*)d_in[4], (const float*)d_in[6], (const float*)d_in[8]};
    const float* Wd = (const float*)d_in[9];
    const float* bd = (const float*)d_in[10];

    float *x, *gates, *seqA, *seqB;
    cudaGetSymbolAddress((void**)&x,     g_x);
    cudaGetSymbolAddress((void**)&gates, g_gates);
    cudaGetSymbolAddress((void**)&seqA,  g_seqA);
    cudaGetSymbolAddress((void**)&seqB,  g_seqB);

    cudaFuncSetAttribute(lstm_layer_k, cudaFuncAttributeMaxDynamicSharedMemorySize,
                         LSTM_SMEM_BYTES);

    // 1) embedding gather
    embed_k<<<TB*EMB/4/256, 256>>>(data, emb, x);

    const float* in = x;
    float* outseq = seqA;
    for (int L = 0; L < 3; L++){
        int Din = (L == 0) ? EMB : HID;
        // 2) input projection for all timesteps: gates = in @ W[:Din] + b
        dim3 gp(G4/128, TB/128);
        sgemm_bias<<<gp, 256>>>(in, W[L], bs[L], gates, TB, G4, Din);
        // 3) persistent recurrence over all 256 steps
        const float* Wh = W[L] + (size_t)Din * G4;
        lstm_layer_k<<<NBLK, 256, LSTM_SMEM_BYTES>>>(gates, Wh, outseq);
        in = outseq;
        outseq = (outseq == seqA) ? seqB : seqA;
    }

    // 4) decoder: logits = in @ Wd + bd
    dim3 gd(VOCAB/128, TB/128);
    sgemm_bias<<<gd, 256>>>(in, Wd, bd, (float*)d_out, TB, VOCAB, HID);
}

// round 3
// speedup vs baseline: 1.8909x; 1.0536x over previous
#include <cuda_runtime.h>
#include <math.h>

#define T_STEPS 256
#define BSZ 32
#define VOCAB 32000
#define EMB 512
#define HID 1024
#define G4 4096
#define TB (T_STEPS*BSZ)   // 8192
#define NBLK 128

// ---------------- scratch (device globals; no allocation allowed) ----------------
__device__ float g_x[TB*EMB];              // 16.8 MB  embedding output
__device__ float g_gates[(size_t)TB*G4];   // 134 MB input-projection gates (per layer, reused)
__device__ float g_seqA[(size_t)TB*HID];   // 33.5 MB layer output ping
__device__ float g_seqB[(size_t)TB*HID];   // 33.5 MB layer output pong

// monotonic grid-barrier counters (striped over 8 L2 addresses, never reset)
__device__ unsigned long long g_ctr[8];

// ---------------- f32x2 packed helpers (sm_103a) ----------------
__device__ __forceinline__ void fma2(unsigned long long &d, unsigned long long a, unsigned long long b){
    asm("fma.rn.f32x2 %0, %1, %2, %0;" : "+l"(d) : "l"(a), "l"(b));
}
__device__ __forceinline__ unsigned long long pk2(float lo, float hi){
    unsigned long long r; asm("mov.b64 %0, {%1, %2};" : "=l"(r) : "f"(lo), "f"(hi)); return r;
}
__device__ __forceinline__ float2 upk2(unsigned long long v){
    float2 r; asm("mov.b64 {%0, %1}, %2;" : "=f"(r.x), "=f"(r.y) : "l"(v)); return r;
}
__device__ __forceinline__ float sigm(float x){ return 1.0f / (1.0f + expf(-x)); }

// ---------------- embedding gather ----------------
__global__ void embed_k(const int* __restrict__ data, const float* __restrict__ emb,
                        float* __restrict__ out){
    int idx = blockIdx.x * 256 + threadIdx.x;
    int e4 = idx & (EMB/4 - 1);
    int tb = idx >> 7;
    ((float4*)out)[idx] = ((const float4*)(emb + (size_t)data[tb]*EMB))[e4];
}

// ---------------- SGEMM: C[M,N] = A[M,K] @ B[K,N] + bias[N] ----------------
// 128x128 tile, BK=16, 256 threads, 8x8 microtile, double-buffered, 1 sync/iter.
__global__ __launch_bounds__(256, 2)
void sgemm_bias(const float* __restrict__ A, const float* __restrict__ Bm,
                const float* __restrict__ bias, float* __restrict__ C,
                int M, int N, int K){
    __shared__ __align__(16) float As[2][16][128];
    __shared__ __align__(16) float Bs[2][16][128];
    const int tid = threadIdx.x;
    const int r0 = blockIdx.y * 128;
    const int c0 = blockIdx.x * 128;
    const int tx = tid & 15;
    const int ty = tid >> 4;

    // staging index precompute
    const int ar0 = tid >> 2,        ac0 = (tid & 3) * 4;          // l=0
    const int ar1 = (tid+256) >> 2,  ac1 = ac0;                    // l=1 (same ac)
    const int br0 = tid >> 5,        bc0 = (tid & 31) * 4;
    const int br1 = (tid+256) >> 5,  bc1 = bc0;

    const float* Aab0 = A + (size_t)(r0 + ar0)*K + ac0;
    const float* Aab1 = A + (size_t)(r0 + ar1)*K + ac1;
    const float* Bab0 = Bm + (size_t)br0*N + c0 + bc0;
    const float* Bab1 = Bm + (size_t)br1*N + c0 + bc1;

    unsigned long long acc[8][4];
    #pragma unroll
    for (int i = 0; i < 8; i++)
        #pragma unroll
        for (int j = 0; j < 4; j++) acc[i][j] = 0ULL;

    // prologue: tile 0
    float4 pa0 = *(const float4*)(Aab0);
    float4 pa1 = *(const float4*)(Aab1);
    float4 pb0 = *(const float4*)(Bab0);
    float4 pb1 = *(const float4*)(Bab1);
    {
        As[0][ac0+0][ar0]=pa0.x; As[0][ac0+1][ar0]=pa0.y; As[0][ac0+2][ar0]=pa0.z; As[0][ac0+3][ar0]=pa0.w;
        As[0][ac1+0][ar1]=pa1.x; As[0][ac1+1][ar1]=pa1.y; As[0][ac1+2][ar1]=pa1.z; As[0][ac1+3][ar1]=pa1.w;
        *(float4*)&Bs[0][br0][bc0] = pb0;
        *(float4*)&Bs[0][br1][bc1] = pb1;
    }
    __syncthreads();

    int buf = 0;
    for (int k0 = 0; k0 < K; k0 += 16){
        int nk = k0 + 16;
        bool more = (nk < K);
        if (more){
            pa0 = *(const float4*)(Aab0 + nk);
            pa1 = *(const float4*)(Aab1 + nk);
            pb0 = *(const float4*)(Bab0 + (size_t)nk*N);
            pb1 = *(const float4*)(Bab1 + (size_t)nk*N);
        }
        #pragma unroll
        for (int k = 0; k < 16; k++){
            float4 a0 = *(const float4*)&As[buf][k][ty*8];
            float4 a1 = *(const float4*)&As[buf][k][ty*8 + 4];
            ulonglong2 b01 = *(const ulonglong2*)&Bs[buf][k][tx*8];
            ulonglong2 b23 = *(const ulonglong2*)&Bs[buf][k][tx*8 + 4];
            float av[8] = {a0.x, a0.y, a0.z, a0.w, a1.x, a1.y, a1.z, a1.w};
            #pragma unroll
            for (int i = 0; i < 8; i++){
                unsigned long long aa = pk2(av[i], av[i]);
                fma2(acc[i][0], aa, b01.x);
                fma2(acc[i][1], aa, b01.y);
                fma2(acc[i][2], aa, b23.x);
                fma2(acc[i][3], aa, b23.y);
            }
        }
        if (more){
            int nb = buf ^ 1;
            As[nb][ac0+0][ar0]=pa0.x; As[nb][ac0+1][ar0]=pa0.y; As[nb][ac0+2][ar0]=pa0.z; As[nb][ac0+3][ar0]=pa0.w;
            As[nb][ac1+0][ar1]=pa1.x; As[nb][ac1+1][ar1]=pa1.y; As[nb][ac1+2][ar1]=pa1.z; As[nb][ac1+3][ar1]=pa1.w;
            *(float4*)&Bs[nb][br0][bc0] = pb0;
            *(float4*)&Bs[nb][br1][bc1] = pb1;
            __syncthreads();
            buf = nb;
        }
    }

    #pragma unroll
    for (int i = 0; i < 8; i++){
        size_t row = (size_t)(r0 + ty*8 + i);
        int col = c0 + tx*8;
        float out[8];
        #pragma unroll
        for (int j = 0; j < 4; j++){
            float2 v = upk2(acc[i][j]);
            out[j*2]   = v.x + bias[col + j*2];
            out[j*2+1] = v.y + bias[col + j*2 + 1];
        }
        *(float4*)(C + row*N + col)     = make_float4(out[0], out[1], out[2], out[3]);
        *(float4*)(C + row*N + col + 4) = make_float4(out[4], out[5], out[6], out[7]);
    }
}

// ---------------- persistent weight-stationary LSTM layer ----------------
// 128 blocks (all co-resident), 512 threads. Each block owns 8 hidden units
// (32 gate cols). Wh slice [1024 x 32] pinned in SMEM. Monotonic grid barrier.
#define SW_F   (1024*32)          // 128 KB
#define SH_F   (512*33)           // 67.6 KB (one 512-k chunk, [k][b] padded)
#define RES_F  (4*4*8*33)         // 16.9 KB  [kq][g][hu][b]
#define SC_F   (8*33)
#define LSTM_SMEM_BYTES ((SW_F + SH_F + RES_F + SC_F) * 4)

__global__ __launch_bounds__(512, 1)
void lstm_layer_k(const float* __restrict__ gates_all,  // [T][32][4096]
                  const float* __restrict__ Wh,         // [1024][4096]
                  float* seq)                           // [T][32][1024]
{
    extern __shared__ float smem[];
    float* sw  = smem;                   // [1024][32]
    float* sh  = sw  + SW_F;             // [512][33]
    float* res = sh  + SH_F;             // [kq][g][hu][33]
    float* sc  = res + RES_F;            // [hu][33]
    __shared__ unsigned long long s_base;

    const int tid = threadIdx.x;
    const int hu0 = blockIdx.x * 8;

    // pin Wh slice
    for (int i = tid; i < SW_F; i += 512){
        int k = i >> 5;
        int c = i & 31;
        int g = c >> 3, hu = c & 7;
        sw[i] = Wh[(size_t)k*G4 + g*HID + hu0 + hu];
    }
    for (int i = tid; i < SC_F; i += 512) sc[i] = 0.f;
    if (tid == 0){
        unsigned long long s = 0;
        #pragma unroll
        for (int i = 0; i < 8; i++) s += ((volatile unsigned long long*)g_ctr)[i];
        s_base = s;
    }
    __syncthreads();
    const unsigned long long base = s_base;

    const int b  = tid & 31;
    const int g  = (tid >> 5) & 3;
    const int kq = tid >> 7;             // 0..3

    const float* swg = sw + g*8;         // column base for this gate

    for (int t = 0; t < T_STEPS; t++){
        unsigned long long acc[4] = {0ULL, 0ULL, 0ULL, 0ULL};

        if (t > 0){
            const float* hprev = seq + (size_t)(t-1)*BSZ*HID;
            #pragma unroll
            for (int cb = 0; cb < 2; cb++){
                // stage 512 k values of h, transposed to [k][b]
                #pragma unroll
                for (int l = 0; l < 8; l++){
                    int idx = tid + l*512;
                    int bb = idx >> 7;
                    int kk = (idx & 127) * 4;
                    float4 v = *(const float4*)(hprev + (size_t)bb*HID + cb*512 + kk);
                    sh[(kk+0)*33 + bb] = v.x;
                    sh[(kk+1)*33 + bb] = v.y;
                    sh[(kk+2)*33 + bb] = v.z;
                    sh[(kk+3)*33 + bb] = v.w;
                }
                __syncthreads();
                const float* shp = sh + (kq*128)*33 + b;
                const float* swp = swg + (size_t)(cb*512 + kq*128)*32;
                #pragma unroll 8
                for (int kk = 0; kk < 128; kk++){
                    float hv = shp[kk*33];
                    unsigned long long h2 = pk2(hv, hv);
                    ulonglong2 w01 = *(const ulonglong2*)(swp + kk*32);
                    ulonglong2 w23 = *(const ulonglong2*)(swp + kk*32 + 4);
                    fma2(acc[0], h2, w01.x);
                    fma2(acc[1], h2, w01.y);
                    fma2(acc[2], h2, w23.x);
                    fma2(acc[3], h2, w23.y);
                }
                __syncthreads();
            }
        }

        // write split-k partials: res[kq][g][hu][b]
        #pragma unroll
        for (int j = 0; j < 4; j++){
            float2 v = upk2(acc[j]);
            res[((kq*4 + g)*8 + j*2    )*33 + b] = v.x;
            res[((kq*4 + g)*8 + j*2 + 1)*33 + b] = v.y;
        }
        __syncthreads();

        // state update (first 256 threads)
        if (tid < 256){
            int hu = tid >> 5;
            int bb = tid & 31;
            const float* gin = gates_all + (size_t)t*BSZ*G4 + (size_t)bb*G4 + hu0 + hu;
            float sg[4];
            #pragma unroll
            for (int gg = 0; gg < 4; gg++){
                float s = 0.f;
                #pragma unroll
                for (int q = 0; q < 4; q++) s += res[((q*4 + gg)*8 + hu)*33 + bb];
                sg[gg] = s;
            }
            float iv = sg[0] + gin[0];
            float gv = sg[1] + gin[HID];
            float fv = sg[2] + gin[2*HID];
            float ov = sg[3] + gin[3*HID];
            float cp = sc[hu*33 + bb];
            float cv = sigm(fv + 1.0f) * cp + sigm(iv) * tanhf(gv);
            float hv = sigm(ov) * tanhf(cv);
            sc[hu*33 + bb] = cv;
            seq[(size_t)t*BSZ*HID + (size_t)bb*HID + hu0 + hu] = hv;
        }

        // grid barrier: striped monotonic counters
        __syncthreads();
        if (tid == 0){
            __threadfence();
            atomicAdd(&g_ctr[blockIdx.x & 7], 1ULL);
            unsigned long long target = base + (unsigned long long)(t+1)*NBLK;
            for (;;){
                unsigned long long s = 0;
                #pragma unroll
                for (int i = 0; i < 8; i++) s += ((volatile unsigned long long*)g_ctr)[i];
                if (s >= target) break;
                __nanosleep(32);
            }
            __threadfence();
        }
        __syncthreads();
    }
}

// ---------------- launch ----------------
extern "C" void kernel_launch(void* const* d_in, const int* in_sizes, int n_in,
                              void* d_out, int out_size){
    (void)in_sizes; (void)n_in; (void)out_size;
    const int*   data = (const int*)d_in[0];
    const float* emb  = (const float*)d_in[2];
    const float* W[3]  = {(const float*)d_in[3], (const float*)d_in[5], (const float*)d_in[7]};
    const float* bs[3] = {(const float*)d_in[4], (const float*)d_in[6], (const float*)d_in[8]};
    const float* Wd = (const float*)d_in[9];
    const float* bd = (const float*)d_in[10];

    float *x, *gates, *seqA, *seqB;
    cudaGetSymbolAddress((void**)&x,     g_x);
    cudaGetSymbolAddress((void**)&gates, g_gates);
    cudaGetSymbolAddress((void**)&seqA,  g_seqA);
    cudaGetSymbolAddress((void**)&seqB,  g_seqB);

    cudaFuncSetAttribute(lstm_layer_k, cudaFuncAttributeMaxDynamicSharedMemorySize,
                         LSTM_SMEM_BYTES);

    // 1) embedding gather
    embed_k<<<TB*EMB/4/256, 256>>>(data, emb, x);

    const float* in = x;
    float* outseq = seqA;
    for (int L = 0; L < 3; L++){
        int Din = (L == 0) ? EMB : HID;
        dim3 gp(G4/128, TB/128);
        sgemm_bias<<<gp, 256>>>(in, W[L], bs[L], gates, TB, G4, Din);
        const float* Wh = W[L] + (size_t)Din * G4;
        lstm_layer_k<<<NBLK, 512, LSTM_SMEM_BYTES>>>(gates, Wh, outseq);
        in = outseq;
        outseq = (outseq == seqA) ? seqB : seqA;
    }

    // 2) decoder: logits = in @ Wd + bd
    dim3 gd(VOCAB/128, TB/128);
    sgemm_bias<<<gd, 256>>>(in, Wd, bd, (float*)d_out, TB, VOCAB, HID);
}

// round 5
// speedup vs baseline: 2.5969x; 1.3734x over previous
#include <cuda_runtime.h>
#include <cuda_bf16.h>
#include <math.h>
#include <cstdint>

#define T_STEPS 256
#define BSZ 32
#define VOCAB 32000
#define EMB 512
#define HID 1024
#define G4 4096
#define TB (T_STEPS*BSZ)   // 8192
#define NBLK 128

// ---------------- scratch (device globals; no allocation allowed) ----------------
__device__ float g_x[TB*EMB];               // 16.8 MB  embedding output
__device__ float g_gates[(size_t)TB*G4];    // 134 MB   input-projection gates
__device__ float g_seqA[(size_t)TB*HID];    // 33.5 MB  layer output ping
__device__ float g_seqB[(size_t)TB*HID];    // 33.5 MB  layer output pong
__device__ __nv_bfloat16 g_ahi[(size_t)TB*HID];      // A split hi
__device__ __nv_bfloat16 g_alo[(size_t)TB*HID];      // A split lo
__device__ __nv_bfloat16 g_wthi[(size_t)G4*HID];     // layer W^T hi
__device__ __nv_bfloat16 g_wtlo[(size_t)G4*HID];     // layer W^T lo
__device__ __nv_bfloat16 g_wdthi[(size_t)VOCAB*HID]; // decoder W^T hi
__device__ __nv_bfloat16 g_wdtlo[(size_t)VOCAB*HID]; // decoder W^T lo

// monotonic grid-barrier counters
__device__ unsigned long long g_ctr[8];

// ---------------- helpers ----------------
__device__ __forceinline__ uint32_t smem_u32(const void* p){
    uint32_t a; asm("{ .reg .u64 t; cvta.to.shared.u64 t, %1; cvt.u32.u64 %0, t; }" : "=r"(a) : "l"(p));
    return a;
}
#define CP_ASYNC16(dst, src) asm volatile("cp.async.cg.shared.global [%0], [%1], 16;" :: "r"(dst), "l"(src))
#define CP_COMMIT()  asm volatile("cp.async.commit_group;" ::: "memory")

__device__ __forceinline__ void ldsm4(uint32_t* r, uint32_t addr){
    asm volatile("ldmatrix.sync.aligned.m8n8.x4.shared.b16 {%0,%1,%2,%3}, [%4];"
        : "=r"(r[0]), "=r"(r[1]), "=r"(r[2]), "=r"(r[3]) : "r"(addr));
}
__device__ __forceinline__ void mma16816(float* c, const uint32_t* a, const uint32_t* b){
    asm volatile("mma.sync.aligned.m16n8k16.row.col.f32.bf16.bf16.f32 "
        "{%0,%1,%2,%3}, {%4,%5,%6,%7}, {%8,%9}, {%0,%1,%2,%3};"
        : "+f"(c[0]), "+f"(c[1]), "+f"(c[2]), "+f"(c[3])
        : "r"(a[0]), "r"(a[1]), "r"(a[2]), "r"(a[3]), "r"(b[0]), "r"(b[1]));
}

// ---------------- f32x2 packed helpers ----------------
__device__ __forceinline__ void fma2(unsigned long long &d, unsigned long long a, unsigned long long b){
    asm("fma.rn.f32x2 %0, %1, %2, %0;" : "+l"(d) : "l"(a), "l"(b));
}
__device__ __forceinline__ unsigned long long pk2(float lo, float hi){
    unsigned long long r; asm("mov.b64 %0, {%1, %2};" : "=l"(r) : "f"(lo), "f"(hi)); return r;
}
__device__ __forceinline__ float2 upk2(unsigned long long v){
    float2 r; asm("mov.b64 {%0, %1}, %2;" : "=f"(r.x), "=f"(r.y) : "l"(v)); return r;
}
__device__ __forceinline__ float sigm(float x){ return 1.0f / (1.0f + expf(-x)); }

// ---------------- embedding gather ----------------
__global__ void embed_k(const int* __restrict__ data, const float* __restrict__ emb,
                        float* __restrict__ out){
    int idx = blockIdx.x * 256 + threadIdx.x;
    int e4 = idx & (EMB/4 - 1);
    int tb = idx >> 7;
    ((float4*)out)[idx] = ((const float4*)(emb + (size_t)data[tb]*EMB))[e4];
}

// ---------------- fp32 -> bf16 hi/lo split ----------------
__global__ void split_k(const float* __restrict__ in, __nv_bfloat16* __restrict__ hi,
                        __nv_bfloat16* __restrict__ lo, int n4){
    int i = blockIdx.x * 256 + threadIdx.x;
    if (i >= n4) return;
    float4 v = ((const float4*)in)[i];
    __nv_bfloat16 h0 = __float2bfloat16(v.x), h1 = __float2bfloat16(v.y);
    __nv_bfloat16 h2 = __float2bfloat16(v.z), h3 = __float2bfloat16(v.w);
    __nv_bfloat16 l0 = __float2bfloat16(v.x - __bfloat162float(h0));
    __nv_bfloat16 l1 = __float2bfloat16(v.y - __bfloat162float(h1));
    __nv_bfloat16 l2 = __float2bfloat16(v.z - __bfloat162float(h2));
    __nv_bfloat16 l3 = __float2bfloat16(v.w - __bfloat162float(h3));
    ((__nv_bfloat162*)hi)[2*i]   = __nv_bfloat162(h0, h1);
    ((__nv_bfloat162*)hi)[2*i+1] = __nv_bfloat162(h2, h3);
    ((__nv_bfloat162*)lo)[2*i]   = __nv_bfloat162(l0, l1);
    ((__nv_bfloat162*)lo)[2*i+1] = __nv_bfloat162(l2, l3);
}

// ---------------- weight transpose + split: W[K,N] -> Wt_hi/lo[N,K] ----------------
__global__ void wtr_k(const float* __restrict__ W, __nv_bfloat16* __restrict__ thi,
                      __nv_bfloat16* __restrict__ tlo, int K, int N){
    __shared__ float s[32][33];
    int tx = threadIdx.x, ty = threadIdx.y;
    int n0 = blockIdx.x * 32, k0 = blockIdx.y * 32;
    #pragma unroll
    for (int j = 0; j < 32; j += 8)
        s[ty+j][tx] = W[(size_t)(k0+ty+j)*N + n0 + tx];
    __syncthreads();
    #pragma unroll
    for (int j = 0; j < 32; j += 8){
        float v = s[tx][ty+j];
        __nv_bfloat16 h = __float2bfloat16(v);
        __nv_bfloat16 l = __float2bfloat16(v - __bfloat162float(h));
        size_t o = (size_t)(n0+ty+j)*K + k0 + tx;
        thi[o] = h;
        tlo[o] = l;
    }
}

// ---------------- bf16 3-split GEMM on mma.sync ----------------
// C[M,N] = Ahi@Bhi^T + Ahi@Blo^T + Alo@Bhi^T + bias.  A:[M,K], Bt:[N,K].
// Tile 128x128, BK=32, 256 thr / 8 warps, warp tile 32x64.
#define BKC 32
#define STRIDE 40                 // bf16 per smem row (32 data + 8 pad = 80 B)
#define MAT_B (128*STRIDE*2)      // 10240 bytes per matrix tile
#define BUF_BYTES (4*MAT_B)       // Ahi,Alo,Bhi,Blo = 40960
#define MMA_SMEM (2*BUF_BYTES + 512)

__global__ __launch_bounds__(256)
void gemm_mma(const __nv_bfloat16* __restrict__ Ahi, const __nv_bfloat16* __restrict__ Alo,
              const __nv_bfloat16* __restrict__ Bhi, const __nv_bfloat16* __restrict__ Blo,
              const float* __restrict__ bias, float* __restrict__ C,
              int M, int N, int K)
{
    extern __shared__ char smem[];
    const uint32_t sb = smem_u32(smem);
    const int tid  = threadIdx.x;
    const int wid  = tid >> 5;
    const int lane = tid & 31;
    const int n0 = blockIdx.x * 128;
    const int m0 = blockIdx.y * 128;
    const int warp_m = (wid & 3) * 32;
    const int warp_n = (wid >> 2) * 64;

    float* biasS = (float*)(smem + 2*BUF_BYTES);
    if (tid < 128) biasS[tid] = bias[n0 + tid];

    // staging mapping: 512 16B-vectors per matrix; 2 per thread
    const int r0v = tid >> 2,          kv0 = (tid & 3) * 8;
    const int r1v = (tid + 256) >> 2,  kv1 = kv0;
    const uint32_t d0 = (uint32_t)(r0v*STRIDE + kv0) * 2;
    const uint32_t d1 = (uint32_t)(r1v*STRIDE + kv1) * 2;

    const __nv_bfloat16* a0p = Ahi + (size_t)(m0 + r0v)*K + kv0;
    const __nv_bfloat16* a1p = Ahi + (size_t)(m0 + r1v)*K + kv1;
    const __nv_bfloat16* l0p = Alo + (size_t)(m0 + r0v)*K + kv0;
    const __nv_bfloat16* l1p = Alo + (size_t)(m0 + r1v)*K + kv1;
    const __nv_bfloat16* b0p = Bhi + (size_t)(n0 + r0v)*K + kv0;
    const __nv_bfloat16* b1p = Bhi + (size_t)(n0 + r1v)*K + kv1;
    const __nv_bfloat16* c0p = Blo + (size_t)(n0 + r0v)*K + kv0;
    const __nv_bfloat16* c1p = Blo + (size_t)(n0 + r1v)*K + kv1;

    // ldmatrix lane offsets (bytes), valid for all 32 lanes (.x4)
    const int lq = lane >> 3, lr = lane & 7;
    uint32_t offA[2], offB[4];
    #pragma unroll
    for (int mt = 0; mt < 2; mt++)
        offA[mt] = (uint32_t)((warp_m + mt*16 + (lq&1)*8 + lr)*STRIDE + (lq>>1)*8) * 2;
    #pragma unroll
    for (int np = 0; np < 4; np++)
        offB[np] = (uint32_t)((warp_n + np*16 + (lq>>1)*8 + lr)*STRIDE + (lq&1)*8) * 2;

    float acc[2][8][4];
    #pragma unroll
    for (int mt = 0; mt < 2; mt++)
        #pragma unroll
        for (int nt = 0; nt < 8; nt++)
            #pragma unroll
            for (int j = 0; j < 4; j++) acc[mt][nt][j] = 0.f;

    const int NC = K / BKC;

    // stage chunk 0
    {
        uint32_t bb = sb;
        CP_ASYNC16(bb + 0*MAT_B + d0, a0p); CP_ASYNC16(bb + 0*MAT_B + d1, a1p);
        CP_ASYNC16(bb + 1*MAT_B + d0, l0p); CP_ASYNC16(bb + 1*MAT_B + d1, l1p);
        CP_ASYNC16(bb + 2*MAT_B + d0, b0p); CP_ASYNC16(bb + 2*MAT_B + d1, b1p);
        CP_ASYNC16(bb + 3*MAT_B + d0, c0p); CP_ASYNC16(bb + 3*MAT_B + d1, c1p);
        CP_COMMIT();
    }

    for (int c = 0; c < NC; c++){
        if (c + 1 < NC){
            uint32_t bb = sb + ((c+1) & 1) * BUF_BYTES;
            int ko = (c+1) * BKC;
            CP_ASYNC16(bb + 0*MAT_B + d0, a0p + ko); CP_ASYNC16(bb + 0*MAT_B + d1, a1p + ko);
            CP_ASYNC16(bb + 1*MAT_B + d0, l0p + ko); CP_ASYNC16(bb + 1*MAT_B + d1, l1p + ko);
            CP_ASYNC16(bb + 2*MAT_B + d0, b0p + ko); CP_ASYNC16(bb + 2*MAT_B + d1, b1p + ko);
            CP_ASYNC16(bb + 3*MAT_B + d0, c0p + ko); CP_ASYNC16(bb + 3*MAT_B + d1, c1p + ko);
            CP_COMMIT();
            asm volatile("cp.async.wait_group 1;" ::: "memory");
        } else {
            asm volatile("cp.async.wait_group 0;" ::: "memory");
        }
        __syncthreads();

        const uint32_t ab = sb + (c & 1) * BUF_BYTES;
        const uint32_t al = ab + MAT_B;
        const uint32_t bh = ab + 2*MAT_B;
        const uint32_t bl = ab + 3*MAT_B;

        #pragma unroll
        for (int ks = 0; ks < 2; ks++){
            const uint32_t ko = ks * 32;   // 16 bf16 = 32 bytes
            uint32_t rah[2][4], ral[2][4];
            #pragma unroll
            for (int mt = 0; mt < 2; mt++){
                ldsm4(rah[mt], ab + offA[mt] + ko);
                ldsm4(ral[mt], al + offA[mt] + ko);
            }
            uint32_t rbh[8][2], rbl[8][2];
            #pragma unroll
            for (int np = 0; np < 4; np++){
                uint32_t t[4];
                ldsm4(t, bh + offB[np] + ko);
                rbh[np*2][0] = t[0];   rbh[np*2][1] = t[1];
                rbh[np*2+1][0] = t[2]; rbh[np*2+1][1] = t[3];
                ldsm4(t, bl + offB[np] + ko);
                rbl[np*2][0] = t[0];   rbl[np*2][1] = t[1];
                rbl[np*2+1][0] = t[2]; rbl[np*2+1][1] = t[3];
            }
            #pragma unroll
            for (int mt = 0; mt < 2; mt++)
                #pragma unroll
                for (int nt = 0; nt < 8; nt++){
                    mma16816(acc[mt][nt], rah[mt], rbh[nt]);
                    mma16816(acc[mt][nt], rah[mt], rbl[nt]);
                    mma16816(acc[mt][nt], ral[mt], rbh[nt]);
                }
        }
        __syncthreads();
    }

    // epilogue
    #pragma unroll
    for (int mt = 0; mt < 2; mt++){
        int row = m0 + warp_m + mt*16 + (lane >> 2);
        #pragma unroll
        for (int nt = 0; nt < 8; nt++){
            int lc = warp_n + nt*8 + (lane & 3)*2;
            float bA = biasS[lc], bB = biasS[lc+1];
            float2 v0 = make_float2(acc[mt][nt][0] + bA, acc[mt][nt][1] + bB);
            float2 v1 = make_float2(acc[mt][nt][2] + bA, acc[mt][nt][3] + bB);
            *(float2*)(C + (size_t)row*N + n0 + lc)       = v0;
            *(float2*)(C + (size_t)(row+8)*N + n0 + lc)   = v1;
        }
    }
}

// ---------------- persistent weight-stationary LSTM layer ----------------
#define SW_F   (1024*32)
#define SH_F   (512*33)
#define RES_F  (4*4*8*33)
#define SC_F   (8*33)
#define LSTM_SMEM_BYTES ((SW_F + SH_F + RES_F + SC_F) * 4)

__global__ __launch_bounds__(512, 1)
void lstm_layer_k(const float* __restrict__ gates_all,
                  const float* __restrict__ Wh,
                  float* seq)
{
    extern __shared__ float fsm[];
    float* sw  = fsm;
    float* sh  = sw  + SW_F;
    float* res = sh  + SH_F;
    float* sc  = res + RES_F;
    __shared__ unsigned long long s_base;

    const int tid = threadIdx.x;
    const int hu0 = blockIdx.x * 8;

    for (int i = tid; i < SW_F; i += 512){
        int k = i >> 5;
        int c = i & 31;
        int g = c >> 3, hu = c & 7;
        sw[i] = Wh[(size_t)k*G4 + g*HID + hu0 + hu];
    }
    for (int i = tid; i < SC_F; i += 512) sc[i] = 0.f;
    if (tid == 0){
        unsigned long long s = 0;
        #pragma unroll
        for (int i = 0; i < 8; i++) s += ((volatile unsigned long long*)g_ctr)[i];
        s_base = s;
    }
    __syncthreads();
    const unsigned long long base = s_base;

    const int b  = tid & 31;
    const int g  = (tid >> 5) & 3;
    const int kq = tid >> 7;

    const float* swg = sw + g*8;

    for (int t = 0; t < T_STEPS; t++){
        unsigned long long acc[4] = {0ULL, 0ULL, 0ULL, 0ULL};

        if (t > 0){
            const float* hprev = seq + (size_t)(t-1)*BSZ*HID;
            #pragma unroll
            for (int cb = 0; cb < 2; cb++){
                #pragma unroll
                for (int l = 0; l < 8; l++){
                    int idx = tid + l*512;
                    int bb = idx >> 7;
                    int kk = (idx & 127) * 4;
                    float4 v = *(const float4*)(hprev + (size_t)bb*HID + cb*512 + kk);
                    sh[(kk+0)*33 + bb] = v.x;
                    sh[(kk+1)*33 + bb] = v.y;
                    sh[(kk+2)*33 + bb] = v.z;
                    sh[(kk+3)*33 + bb] = v.w;
                }
                __syncthreads();
                const float* shp = sh + (kq*128)*33 + b;
                const float* swp = swg + (size_t)(cb*512 + kq*128)*32;
                #pragma unroll 8
                for (int kk = 0; kk < 128; kk++){
                    float hv = shp[kk*33];
                    unsigned long long h2 = pk2(hv, hv);
                    ulonglong2 w01 = *(const ulonglong2*)(swp + kk*32);
                    ulonglong2 w23 = *(const ulonglong2*)(swp + kk*32 + 4);
                    fma2(acc[0], h2, w01.x);
                    fma2(acc[1], h2, w01.y);
                    fma2(acc[2], h2, w23.x);
                    fma2(acc[3], h2, w23.y);
                }
                __syncthreads();
            }
        }

        #pragma unroll
        for (int j = 0; j < 4; j++){
            float2 v = upk2(acc[j]);
            res[((kq*4 + g)*8 + j*2    )*33 + b] = v.x;
            res[((kq*4 + g)*8 + j*2 + 1)*33 + b] = v.y;
        }
        __syncthreads();

        if (tid < 256){
            int hu = tid >> 5;
            int bb = tid & 31;
            const float* gin = gates_all + (size_t)t*BSZ*G4 + (size_t)bb*G4 + hu0 + hu;
            float sg[4];
            #pragma unroll
            for (int gg = 0; gg < 4; gg++){
                float s = 0.f;
                #pragma unroll
                for (int q = 0; q < 4; q++) s += res[((q*4 + gg)*8 + hu)*33 + bb];
                sg[gg] = s;
            }
            float iv = sg[0] + gin[0];
            float gv = sg[1] + gin[HID];
            float fv = sg[2] + gin[2*HID];
            float ov = sg[3] + gin[3*HID];
            float cp = sc[hu*33 + bb];
            float cv = sigm(fv + 1.0f) * cp + sigm(iv) * tanhf(gv);
            float hv = sigm(ov) * tanhf(cv);
            sc[hu*33 + bb] = cv;
            seq[(size_t)t*BSZ*HID + (size_t)bb*HID + hu0 + hu] = hv;
        }

        __syncthreads();
        if (tid == 0){
            __threadfence();
            atomicAdd(&g_ctr[blockIdx.x & 7], 1ULL);
            unsigned long long target = base + (unsigned long long)(t+1)*NBLK;
            for (;;){
                unsigned long long s = 0;
                #pragma unroll
                for (int i = 0; i < 8; i++) s += ((volatile unsigned long long*)g_ctr)[i];
                if (s >= target) break;
                __nanosleep(32);
            }
            __threadfence();
        }
        __syncthreads();
    }
}

// ---------------- launch ----------------
extern "C" void kernel_launch(void* const* d_in, const int* in_sizes, int n_in,
                              void* d_out, int out_size){
    (void)in_sizes; (void)n_in; (void)out_size;
    const int*   data = (const int*)d_in[0];
    const float* emb  = (const float*)d_in[2];
    const float* W[3]  = {(const float*)d_in[3], (const float*)d_in[5], (const float*)d_in[7]};
    const float* bs[3] = {(const float*)d_in[4], (const float*)d_in[6], (const float*)d_in[8]};
    const float* Wd = (const float*)d_in[9];
    const float* bd = (const float*)d_in[10];

    float *x, *gates, *seqA, *seqB;
    __nv_bfloat16 *ahi, *alo, *wthi, *wtlo, *wdthi, *wdtlo;
    cudaGetSymbolAddress((void**)&x,     g_x);
    cudaGetSymbolAddress((void**)&gates, g_gates);
    cudaGetSymbolAddress((void**)&seqA,  g_seqA);
    cudaGetSymbolAddress((void**)&seqB,  g_seqB);
    cudaGetSymbolAddress((void**)&ahi,   g_ahi);
    cudaGetSymbolAddress((void**)&alo,   g_alo);
    cudaGetSymbolAddress((void**)&wthi,  g_wthi);
    cudaGetSymbolAddress((void**)&wtlo,  g_wtlo);
    cudaGetSymbolAddress((void**)&wdthi, g_wdthi);
    cudaGetSymbolAddress((void**)&wdtlo, g_wdtlo);

    cudaFuncSetAttribute(lstm_layer_k, cudaFuncAttributeMaxDynamicSharedMemorySize,
                         LSTM_SMEM_BYTES);
    cudaFuncSetAttribute(gemm_mma, cudaFuncAttributeMaxDynamicSharedMemorySize,
                         MMA_SMEM);

    // 1) embedding gather
    embed_k<<<TB*EMB/4/256, 256>>>(data, emb, x);

    const float* in = x;
    float* outseq = seqA;
    for (int L = 0; L < 3; L++){
        int Din = (L == 0) ? EMB : HID;
        split_k<<<(TB*Din/4 + 255)/256, 256>>>(in, ahi, alo, TB*Din/4);
        wtr_k<<<dim3(G4/32, Din/32), dim3(32, 8)>>>(W[L], wthi, wtlo, Din, G4);
        gemm_mma<<<dim3(G4/128, TB/128), 256, MMA_SMEM>>>(
            ahi, alo, wthi, wtlo, bs[L], gates, TB, G4, Din);
        const float* Wh = W[L] + (size_t)Din * G4;
        lstm_layer_k<<<NBLK, 512, LSTM_SMEM_BYTES>>>(gates, Wh, outseq);
        in = outseq;
        outseq = (outseq == seqA) ? seqB : seqA;
    }

    // 2) decoder
    split_k<<<(TB*HID/4 + 255)/256, 256>>>(in, ahi, alo, TB*HID/4);
    wtr_k<<<dim3(VOCAB/32, HID/32), dim3(32, 8)>>>(Wd, wdthi, wdtlo, HID, VOCAB);
    gemm_mma<<<dim3(VOCAB/128, TB/128), 256, MMA_SMEM>>>(
        ahi, alo, wdthi, wdtlo, bd, (float*)d_out, TB, VOCAB, HID);
}

// round 7
// speedup vs baseline: 3.6626x; 1.4104x over previous
#include <cuda_runtime.h>
#include <cuda_bf16.h>
#include <math.h>
#include <cstdint>

#define T_STEPS 256
#define BSZ 32
#define VOCAB 32000
#define EMB 512
#define HID 1024
#define G4 4096
#define TB (T_STEPS*BSZ)   // 8192
#define NBLK 128

// ---------------- scratch (device globals; no allocation allowed) ----------------
__device__ float g_x[TB*EMB];               // 16.8 MB  embedding output
__device__ float g_gates[(size_t)TB*G4];    // 134 MB   input-projection gates
__device__ float g_seqA[(size_t)TB*HID];    // 33.5 MB  layer output ping
__device__ float g_seqB[(size_t)TB*HID];    // 33.5 MB  layer output pong
__device__ __nv_bfloat16 g_ahi[(size_t)TB*HID];      // A split hi
__device__ __nv_bfloat16 g_alo[(size_t)TB*HID];      // A split lo
__device__ __nv_bfloat16 g_wthi[(size_t)G4*HID];     // layer Wx^T hi
__device__ __nv_bfloat16 g_wtlo[(size_t)G4*HID];     // layer Wx^T lo
__device__ __nv_bfloat16 g_whthi[(size_t)G4*HID];    // layer Wh^T hi
__device__ __nv_bfloat16 g_whtlo[(size_t)G4*HID];    // layer Wh^T lo
__device__ __nv_bfloat16 g_wdthi[(size_t)VOCAB*HID]; // decoder W^T hi
__device__ __nv_bfloat16 g_wdtlo[(size_t)VOCAB*HID]; // decoder W^T lo
__device__ __nv_bfloat16 g_hb[2*2*BSZ*HID];          // h bf16 [par][hi/lo][32*1024]

// monotonic grid-barrier counter
__device__ unsigned long long g_ctr1;

// ---------------- helpers ----------------
__device__ __forceinline__ uint32_t smem_u32(const void* p){
    uint32_t a; asm("{ .reg .u64 t; cvta.to.shared.u64 t, %1; cvt.u32.u64 %0, t; }" : "=r"(a) : "l"(p));
    return a;
}
#define CP_ASYNC16(dst, src) asm volatile("cp.async.cg.shared.global [%0], [%1], 16;" :: "r"(dst), "l"(src))
#define CP_COMMIT()  asm volatile("cp.async.commit_group;" ::: "memory")

__device__ __forceinline__ void ldsm4(uint32_t* r, uint32_t addr){
    asm volatile("ldmatrix.sync.aligned.m8n8.x4.shared.b16 {%0,%1,%2,%3}, [%4];"
        : "=r"(r[0]), "=r"(r[1]), "=r"(r[2]), "=r"(r[3]) : "r"(addr));
}
__device__ __forceinline__ void mma16816(float* c, const uint32_t* a, const uint32_t* b){
    asm volatile("mma.sync.aligned.m16n8k16.row.col.f32.bf16.bf16.f32 "
        "{%0,%1,%2,%3}, {%4,%5,%6,%7}, {%8,%9}, {%0,%1,%2,%3};"
        : "+f"(c[0]), "+f"(c[1]), "+f"(c[2]), "+f"(c[3])
        : "r"(a[0]), "r"(a[1]), "r"(a[2]), "r"(a[3]), "r"(b[0]), "r"(b[1]));
}
__device__ __forceinline__ float sigm(float x){ return 1.0f / (1.0f + expf(-x)); }

// ---------------- embedding gather ----------------
__global__ void embed_k(const int* __restrict__ data, const float* __restrict__ emb,
                        float* __restrict__ out){
    int idx = blockIdx.x * 256 + threadIdx.x;
    int e4 = idx & (EMB/4 - 1);
    int tb = idx >> 7;
    ((float4*)out)[idx] = ((const float4*)(emb + (size_t)data[tb]*EMB))[e4];
}

// ---------------- fp32 -> bf16 hi/lo split ----------------
__global__ void split_k(const float* __restrict__ in, __nv_bfloat16* __restrict__ hi,
                        __nv_bfloat16* __restrict__ lo, int n4){
    int i = blockIdx.x * 256 + threadIdx.x;
    if (i >= n4) return;
    float4 v = ((const float4*)in)[i];
    __nv_bfloat16 h0 = __float2bfloat16(v.x), h1 = __float2bfloat16(v.y);
    __nv_bfloat16 h2 = __float2bfloat16(v.z), h3 = __float2bfloat16(v.w);
    __nv_bfloat16 l0 = __float2bfloat16(v.x - __bfloat162float(h0));
    __nv_bfloat16 l1 = __float2bfloat16(v.y - __bfloat162float(h1));
    __nv_bfloat16 l2 = __float2bfloat16(v.z - __bfloat162float(h2));
    __nv_bfloat16 l3 = __float2bfloat16(v.w - __bfloat162float(h3));
    ((__nv_bfloat162*)hi)[2*i]   = __nv_bfloat162(h0, h1);
    ((__nv_bfloat162*)hi)[2*i+1] = __nv_bfloat162(h2, h3);
    ((__nv_bfloat162*)lo)[2*i]   = __nv_bfloat162(l0, l1);
    ((__nv_bfloat162*)lo)[2*i+1] = __nv_bfloat162(l2, l3);
}

// ---------------- weight transpose + split: W[K,N] -> Wt_hi/lo[N,K] ----------------
__global__ void wtr_k(const float* __restrict__ W, __nv_bfloat16* __restrict__ thi,
                      __nv_bfloat16* __restrict__ tlo, int K, int N){
    __shared__ float s[32][33];
    int tx = threadIdx.x, ty = threadIdx.y;
    int n0 = blockIdx.x * 32, k0 = blockIdx.y * 32;
    #pragma unroll
    for (int j = 0; j < 32; j += 8)
        s[ty+j][tx] = W[(size_t)(k0+ty+j)*N + n0 + tx];
    __syncthreads();
    #pragma unroll
    for (int j = 0; j < 32; j += 8){
        float v = s[tx][ty+j];
        __nv_bfloat16 h = __float2bfloat16(v);
        __nv_bfloat16 l = __float2bfloat16(v - __bfloat162float(h));
        size_t o = (size_t)(n0+ty+j)*K + k0 + tx;
        thi[o] = h;
        tlo[o] = l;
    }
}

// ---------------- bf16 3-split GEMM on mma.sync ----------------
#define BKC 32
#define STRIDE 40
#define MAT_B (128*STRIDE*2)
#define BUF_BYTES (4*MAT_B)
#define MMA_SMEM (2*BUF_BYTES + 512)

__global__ __launch_bounds__(256)
void gemm_mma(const __nv_bfloat16* __restrict__ Ahi, const __nv_bfloat16* __restrict__ Alo,
              const __nv_bfloat16* __restrict__ Bhi, const __nv_bfloat16* __restrict__ Blo,
              const float* __restrict__ bias, float* __restrict__ C,
              int M, int N, int K)
{
    extern __shared__ char smem[];
    const uint32_t sb = smem_u32(smem);
    const int tid  = threadIdx.x;
    const int wid  = tid >> 5;
    const int lane = tid & 31;
    const int n0 = blockIdx.x * 128;
    const int m0 = blockIdx.y * 128;
    const int warp_m = (wid & 3) * 32;
    const int warp_n = (wid >> 2) * 64;

    float* biasS = (float*)(smem + 2*BUF_BYTES);
    if (tid < 128) biasS[tid] = bias[n0 + tid];

    const int r0v = tid >> 2,          kv0 = (tid & 3) * 8;
    const int r1v = (tid + 256) >> 2,  kv1 = kv0;
    const uint32_t d0 = (uint32_t)(r0v*STRIDE + kv0) * 2;
    const uint32_t d1 = (uint32_t)(r1v*STRIDE + kv1) * 2;

    const __nv_bfloat16* a0p = Ahi + (size_t)(m0 + r0v)*K + kv0;
    const __nv_bfloat16* a1p = Ahi + (size_t)(m0 + r1v)*K + kv1;
    const __nv_bfloat16* l0p = Alo + (size_t)(m0 + r0v)*K + kv0;
    const __nv_bfloat16* l1p = Alo + (size_t)(m0 + r1v)*K + kv1;
    const __nv_bfloat16* b0p = Bhi + (size_t)(n0 + r0v)*K + kv0;
    const __nv_bfloat16* b1p = Bhi + (size_t)(n0 + r1v)*K + kv1;
    const __nv_bfloat16* c0p = Blo + (size_t)(n0 + r0v)*K + kv0;
    const __nv_bfloat16* c1p = Blo + (size_t)(n0 + r1v)*K + kv1;

    const int lq = lane >> 3, lr = lane & 7;
    uint32_t offA[2], offB[4];
    #pragma unroll
    for (int mt = 0; mt < 2; mt++)
        offA[mt] = (uint32_t)((warp_m + mt*16 + (lq&1)*8 + lr)*STRIDE + (lq>>1)*8) * 2;
    #pragma unroll
    for (int np = 0; np < 4; np++)
        offB[np] = (uint32_t)((warp_n + np*16 + (lq>>1)*8 + lr)*STRIDE + (lq&1)*8) * 2;

    float acc[2][8][4];
    #pragma unroll
    for (int mt = 0; mt < 2; mt++)
        #pragma unroll
        for (int nt = 0; nt < 8; nt++)
            #pragma unroll
            for (int j = 0; j < 4; j++) acc[mt][nt][j] = 0.f;

    const int NC = K / BKC;

    {
        uint32_t bb = sb;
        CP_ASYNC16(bb + 0*MAT_B + d0, a0p); CP_ASYNC16(bb + 0*MAT_B + d1, a1p);
        CP_ASYNC16(bb + 1*MAT_B + d0, l0p); CP_ASYNC16(bb + 1*MAT_B + d1, l1p);
        CP_ASYNC16(bb + 2*MAT_B + d0, b0p); CP_ASYNC16(bb + 2*MAT_B + d1, b1p);
        CP_ASYNC16(bb + 3*MAT_B + d0, c0p); CP_ASYNC16(bb + 3*MAT_B + d1, c1p);
        CP_COMMIT();
    }

    for (int c = 0; c < NC; c++){
        if (c + 1 < NC){
            uint32_t bb = sb + ((c+1) & 1) * BUF_BYTES;
            int ko = (c+1) * BKC;
            CP_ASYNC16(bb + 0*MAT_B + d0, a0p + ko); CP_ASYNC16(bb + 0*MAT_B + d1, a1p + ko);
            CP_ASYNC16(bb + 1*MAT_B + d0, l0p + ko); CP_ASYNC16(bb + 1*MAT_B + d1, l1p + ko);
            CP_ASYNC16(bb + 2*MAT_B + d0, b0p + ko); CP_ASYNC16(bb + 2*MAT_B + d1, b1p + ko);
            CP_ASYNC16(bb + 3*MAT_B + d0, c0p + ko); CP_ASYNC16(bb + 3*MAT_B + d1, c1p + ko);
            CP_COMMIT();
            asm volatile("cp.async.wait_group 1;" ::: "memory");
        } else {
            asm volatile("cp.async.wait_group 0;" ::: "memory");
        }
        __syncthreads();

        const uint32_t ab = sb + (c & 1) * BUF_BYTES;
        const uint32_t al = ab + MAT_B;
        const uint32_t bh = ab + 2*MAT_B;
        const uint32_t bl = ab + 3*MAT_B;

        #pragma unroll
        for (int ks = 0; ks < 2; ks++){
            const uint32_t ko = ks * 32;
            uint32_t rah[2][4], ral[2][4];
            #pragma unroll
            for (int mt = 0; mt < 2; mt++){
                ldsm4(rah[mt], ab + offA[mt] + ko);
                ldsm4(ral[mt], al + offA[mt] + ko);
            }
            uint32_t rbh[8][2], rbl[8][2];
            #pragma unroll
            for (int np = 0; np < 4; np++){
                uint32_t t[4];
                ldsm4(t, bh + offB[np] + ko);
                rbh[np*2][0] = t[0];   rbh[np*2][1] = t[1];
                rbh[np*2+1][0] = t[2]; rbh[np*2+1][1] = t[3];
                ldsm4(t, bl + offB[np] + ko);
                rbl[np*2][0] = t[0];   rbl[np*2][1] = t[1];
                rbl[np*2+1][0] = t[2]; rbl[np*2+1][1] = t[3];
            }
            #pragma unroll
            for (int mt = 0; mt < 2; mt++)
                #pragma unroll
                for (int nt = 0; nt < 8; nt++){
                    mma16816(acc[mt][nt], rah[mt], rbh[nt]);
                    mma16816(acc[mt][nt], rah[mt], rbl[nt]);
                    mma16816(acc[mt][nt], ral[mt], rbh[nt]);
                }
        }
        __syncthreads();
    }

    #pragma unroll
    for (int mt = 0; mt < 2; mt++){
        int row = m0 + warp_m + mt*16 + (lane >> 2);
        #pragma unroll
        for (int nt = 0; nt < 8; nt++){
            int lc = warp_n + nt*8 + (lane & 3)*2;
            float bA = biasS[lc], bB = biasS[lc+1];
            float2 v0 = make_float2(acc[mt][nt][0] + bA, acc[mt][nt][1] + bB);
            float2 v1 = make_float2(acc[mt][nt][2] + bA, acc[mt][nt][3] + bB);
            *(float2*)(C + (size_t)row*N + n0 + lc)       = v0;
            *(float2*)(C + (size_t)(row+8)*N + n0 + lc)   = v1;
        }
    }
}

// ---------------- persistent tensor-core LSTM layer ----------------
// 128 blocks, 256 thr / 8 warps. Block owns 32 gate cols (4 gates x 8 units).
// Wh^T bf16 fragments live in REGISTERS (loaded once per layer).
// h exchanged as bf16 hi/lo via small double-buffered global; A-frags via direct LDG.
__global__ __launch_bounds__(256, 1)
void lstm_layer_mma(const float* __restrict__ gates_all,   // [T][32][4096]
                    const __nv_bfloat16* __restrict__ whhi, // [4096][1024]
                    const __nv_bfloat16* __restrict__ whlo,
                    float* __restrict__ seq,                // [T][32][1024]
                    __nv_bfloat16* __restrict__ hb)         // [2][2][32*1024]
{
    __shared__ float red[8][32][34];   // [warp][row(b)][col] (pad 34 for STS.64)
    __shared__ float sc[8][33];        // cell state [unit][b]
    __shared__ unsigned long long s_base;

    const int tid  = threadIdx.x;
    const int w    = tid >> 5;
    const int lane = tid & 31;
    const int hu0  = blockIdx.x * 8;
    const int wk0  = w * 128;          // warp k-slice base
    const int qr   = lane >> 2;        // 0..7
    const int qc   = (lane & 3) * 2;   // 0,2,4,6

    // --- B fragments (Wh^T hi/lo) once per layer: [gate][ktile][2 regs] ---
    uint32_t bh[4][8][2], bl[4][8][2];
    #pragma unroll
    for (int g = 0; g < 4; g++){
        const size_t col = (size_t)(g*1024 + hu0 + qr);
        #pragma unroll
        for (int kt = 0; kt < 8; kt++){
            const size_t kk = (size_t)wk0 + kt*16 + qc;
            bh[g][kt][0] = *(const uint32_t*)(whhi + col*HID + kk);
            bh[g][kt][1] = *(const uint32_t*)(whhi + col*HID + kk + 8);
            bl[g][kt][0] = *(const uint32_t*)(whlo + col*HID + kk);
            bl[g][kt][1] = *(const uint32_t*)(whlo + col*HID + kk + 8);
        }
    }

    for (int i = tid; i < 8*33; i += 256) ((float*)sc)[i] = 0.f;
    if (tid == 0) s_base = *(volatile unsigned long long*)&g_ctr1;
    __syncthreads();
    const unsigned long long base = s_base;

    const int ub = tid & 31;    // update: batch
    const int uj = tid >> 5;    // update: unit 0..7

    for (int t = 0; t < T_STEPS; t++){
        float acc[2][4][4];
        #pragma unroll
        for (int mt = 0; mt < 2; mt++)
            #pragma unroll
            for (int g = 0; g < 4; g++)
                #pragma unroll
                for (int j = 0; j < 4; j++) acc[mt][g][j] = 0.f;

        if (t > 0){
            const __nv_bfloat16* hhi = hb + (size_t)(t & 1) * (2*BSZ*HID);
            const __nv_bfloat16* hlo = hhi + BSZ*HID;
            #pragma unroll 2
            for (int kt = 0; kt < 8; kt++){
                const int kk = wk0 + kt*16 + qc;
                uint32_t ah[2][4], al[2][4];
                #pragma unroll
                for (int mt = 0; mt < 2; mt++){
                    const int r = mt*16 + qr;
                    ah[mt][0] = *(const uint32_t*)(hhi + r*HID + kk);
                    ah[mt][1] = *(const uint32_t*)(hhi + (r+8)*HID + kk);
                    ah[mt][2] = *(const uint32_t*)(hhi + r*HID + kk + 8);
                    ah[mt][3] = *(const uint32_t*)(hhi + (r+8)*HID + kk + 8);
                    al[mt][0] = *(const uint32_t*)(hlo + r*HID + kk);
                    al[mt][1] = *(const uint32_t*)(hlo + (r+8)*HID + kk);
                    al[mt][2] = *(const uint32_t*)(hlo + r*HID + kk + 8);
                    al[mt][3] = *(const uint32_t*)(hlo + (r+8)*HID + kk + 8);
                }
                #pragma unroll
                for (int mt = 0; mt < 2; mt++)
                    #pragma unroll
                    for (int g = 0; g < 4; g++){
                        mma16816(acc[mt][g], ah[mt], bh[g][kt]);
                        mma16816(acc[mt][g], ah[mt], bl[g][kt]);
                        mma16816(acc[mt][g], al[mt], bh[g][kt]);
                    }
            }
        }

        // split-k partials -> smem
        #pragma unroll
        for (int mt = 0; mt < 2; mt++)
            #pragma unroll
            for (int g = 0; g < 4; g++){
                const int r = mt*16 + qr;
                *(float2*)&red[w][r][g*8 + qc]   = make_float2(acc[mt][g][0], acc[mt][g][1]);
                *(float2*)&red[w][r+8][g*8 + qc] = make_float2(acc[mt][g][2], acc[mt][g][3]);
            }
        __syncthreads();

        // state update: thread = (batch ub, unit uj)
        {
            float sg[4] = {0.f, 0.f, 0.f, 0.f};
            #pragma unroll
            for (int ww = 0; ww < 8; ww++)
                #pragma unroll
                for (int g = 0; g < 4; g++)
                    sg[g] += red[ww][ub][g*8 + uj];

            const float* gin = gates_all + (size_t)t*BSZ*G4 + (size_t)ub*G4 + hu0 + uj;
            float iv = sg[0] + gin[0];
            float gv = sg[1] + gin[HID];
            float fv = sg[2] + gin[2*HID];
            float ov = sg[3] + gin[3*HID];
            float cp = sc[uj][ub];
            float cv = sigm(fv + 1.0f) * cp + sigm(iv) * tanhf(gv);
            float hv = sigm(ov) * tanhf(cv);
            sc[uj][ub] = cv;
            seq[(size_t)t*BSZ*HID + (size_t)ub*HID + hu0 + uj] = hv;

            __nv_bfloat16 hhv = __float2bfloat16(hv);
            __nv_bfloat16 hlv = __float2bfloat16(hv - __bfloat162float(hhv));
            __nv_bfloat16* wbuf = hb + (size_t)((t+1) & 1) * (2*BSZ*HID);
            wbuf[ub*HID + hu0 + uj]           = hhv;
            wbuf[BSZ*HID + ub*HID + hu0 + uj] = hlv;
        }

        // grid barrier (publishes h(t))
        __syncthreads();
        if (tid == 0){
            __threadfence();
            atomicAdd(&g_ctr1, 1ULL);
            const unsigned long long target = base + (unsigned long long)(t+1)*NBLK;
            while (*(volatile unsigned long long*)&g_ctr1 < target) __nanosleep(64);
            __threadfence();
        }
        __syncthreads();
    }
}

// ---------------- launch ----------------
extern "C" void kernel_launch(void* const* d_in, const int* in_sizes, int n_in,
                              void* d_out, int out_size){
    (void)in_sizes; (void)n_in; (void)out_size;
    const int*   data = (const int*)d_in[0];
    const float* emb  = (const float*)d_in[2];
    const float* W[3]  = {(const float*)d_in[3], (const float*)d_in[5], (const float*)d_in[7]};
    const float* bs[3] = {(const float*)d_in[4], (const float*)d_in[6], (const float*)d_in[8]};
    const float* Wd = (const float*)d_in[9];
    const float* bd = (const float*)d_in[10];

    float *x, *gates, *seqA, *seqB;
    __nv_bfloat16 *ahi, *alo, *wthi, *wtlo, *whthi, *whtlo, *wdthi, *wdtlo, *hb;
    cudaGetSymbolAddress((void**)&x,     g_x);
    cudaGetSymbolAddress((void**)&gates, g_gates);
    cudaGetSymbolAddress((void**)&seqA,  g_seqA);
    cudaGetSymbolAddress((void**)&seqB,  g_seqB);
    cudaGetSymbolAddress((void**)&ahi,   g_ahi);
    cudaGetSymbolAddress((void**)&alo,   g_alo);
    cudaGetSymbolAddress((void**)&wthi,  g_wthi);
    cudaGetSymbolAddress((void**)&wtlo,  g_wtlo);
    cudaGetSymbolAddress((void**)&whthi, g_whthi);
    cudaGetSymbolAddress((void**)&whtlo, g_whtlo);
    cudaGetSymbolAddress((void**)&wdthi, g_wdthi);
    cudaGetSymbolAddress((void**)&wdtlo, g_wdtlo);
    cudaGetSymbolAddress((void**)&hb,    g_hb);

    cudaFuncSetAttribute(gemm_mma, cudaFuncAttributeMaxDynamicSharedMemorySize, MMA_SMEM);

    // 1) embedding gather
    embed_k<<<TB*EMB/4/256, 256>>>(data, emb, x);

    const float* in = x;
    float* outseq = seqA;
    for (int L = 0; L < 3; L++){
        int Din = (L == 0) ? EMB : HID;
        // input projection on tensor cores
        split_k<<<(TB*Din/4 + 255)/256, 256>>>(in, ahi, alo, TB*Din/4);
        wtr_k<<<dim3(G4/32, Din/32), dim3(32, 8)>>>(W[L], wthi, wtlo, Din, G4);
        gemm_mma<<<dim3(G4/128, TB/128), 256, MMA_SMEM>>>(
            ahi, alo, wthi, wtlo, bs[L], gates, TB, G4, Din);
        // recurrent weights -> bf16 split, then persistent tensor-core recurrence
        const float* Wh = W[L] + (size_t)Din * G4;
        wtr_k<<<dim3(G4/32, HID/32), dim3(32, 8)>>>(Wh, whthi, whtlo, HID, G4);
        lstm_layer_mma<<<NBLK, 256>>>(gates, whthi, whtlo, outseq, hb);
        in = outseq;
        outseq = (outseq == seqA) ? seqB : seqA;
    }

    // 2) decoder on tensor cores
    split_k<<<(TB*HID/4 + 255)/256, 256>>>(in, ahi, alo, TB*HID/4);
    wtr_k<<<dim3(VOCAB/32, HID/32), dim3(32, 8)>>>(Wd, wdthi, wdtlo, HID, VOCAB);
    gemm_mma<<<dim3(VOCAB/128, TB/128), 256, MMA_SMEM>>>(
        ahi, alo, wdthi, wdtlo, bd, (float*)d_out, TB, VOCAB, HID);
}